// round 8
// baseline (speedup 1.0000x reference)
#include <cuda_runtime.h>

// ArnoldCat ^7, n=1024: out[a,b] <- in[(239a+169b)&1023, (338a+239b)&1023].
//
// Lattice basis: (a,b) = (169k', j'-239k'), source = (169j', k'+239j').
// Tile (m,n): k'=32m+k, j'=32n+j. Exact partition both directions (R7 addressing,
// stride-99 output-ordered SMEM: STS/LDS addr ≡ lane (mod 32), conflict-free).
//
// R8: 4 consecutive-n tiles per block, ping-pong SMEM software pipeline.
// Steady state: tile t+1 loads are issued BEFORE tile t's store burst, so the
// DRAM read queue never drains during the write phase. Same traffic as R7.

static constexpr unsigned THREADS = 256u;
static constexpr unsigned BLOCKS  = 16u * 32u * 8u;    // batch x m x nq(8) = 4096
static constexpr unsigned IMG_F   = 1024u * 3072u;

__global__ void __launch_bounds__(THREADS)
arnold_v8_kernel(const float* __restrict__ in, float* __restrict__ out) {
    __shared__ float osm[2][3168];                     // 2 x 32 x 99 floats

    const unsigned id    = blockIdx.x;
    const unsigned nq    = id & 7u;                    // n = 4*nq + t
    const unsigned m     = (id >> 3) & 31u;
    const unsigned batch = id >> 8;
    const unsigned lane  = threadIdx.x & 31u;
    const unsigned warp  = threadIdx.x >> 5;           // 0..7

    const float* inb  = in  + batch * IMG_F;
    float*       outb = out + batch * IMG_F;

    // element f = lane+32t -> smem base 99*(f/3) + f%3
    unsigned sb[3];
    #pragma unroll
    for (unsigned t = 0; t < 3u; ++t) {
        unsigned f = lane + 32u * t;
        unsigned k = f / 3u;
        sb[t] = 99u * k + (f - 3u * k);
    }

    auto load_tile = [&](unsigned n, float v[4][3]) {
        #pragma unroll
        for (unsigned r = 0; r < 4u; ++r) {
            unsigned j   = warp + 8u * r;
            unsigned jp  = 32u * n + j;
            unsigned ry  = (169u * jp) & 1023u;
            unsigned cb3 = ((32u * m + 239u * jp) & 1023u) * 3u;
            const float* rowp = inb + ry * 3072u;
            if (cb3 <= 3072u - 96u) {                  // warp-uniform fast path
                const float* seg = rowp + cb3 + lane;
                v[r][0] = __ldcs(seg);
                v[r][1] = __ldcs(seg + 32u);
                v[r][2] = __ldcs(seg + 64u);
            } else {
                #pragma unroll
                for (unsigned t = 0; t < 3u; ++t) {
                    unsigned o = cb3 + lane + 32u * t;
                    if (o >= 3072u) o -= 3072u;
                    v[r][t] = __ldcs(rowp + o);
                }
            }
        }
    };

    auto sts_tile = [&](float* buf, float v[4][3]) {
        #pragma unroll
        for (unsigned r = 0; r < 4u; ++r) {
            unsigned j3 = 3u * (warp + 8u * r);
            #pragma unroll
            for (unsigned t = 0; t < 3u; ++t)
                buf[sb[t] + j3] = v[r][t];
        }
    };

    auto stg_tile = [&](const float* buf, unsigned n) {
        #pragma unroll
        for (unsigned it = 0; it < 4u; ++it) {
            unsigned k   = warp + 8u * it;
            unsigned kp  = 32u * m + k;
            unsigned a   = (169u * kp) & 1023u;
            unsigned ob3 = ((32u * n - 239u * kp) & 1023u) * 3u;
            const float* sr = buf + 99u * k + lane;
            float r0 = sr[0], r1 = sr[32], r2 = sr[64];
            float* orow = outb + a * 3072u;
            if (ob3 <= 3072u - 96u) {                  // warp-uniform fast path
                float* seg = orow + ob3 + lane;
                __stcs(seg,       r0);
                __stcs(seg + 32u, r1);
                __stcs(seg + 64u, r2);
            } else {
                float rr[3] = {r0, r1, r2};
                #pragma unroll
                for (unsigned t = 0; t < 3u; ++t) {
                    unsigned o = ob3 + lane + 32u * t;
                    if (o >= 3072u) o -= 3072u;
                    __stcs(orow + o, rr[t]);
                }
            }
        }
    };

    const unsigned n0 = nq * 4u;
    float v[4][3];

    load_tile(n0, v);
    sts_tile(osm[0], v);
    __syncthreads();

    #pragma unroll
    for (unsigned t = 1; t < 4u; ++t) {
        load_tile(n0 + t, v);                 // LDGs in flight under the store burst
        stg_tile(osm[(t - 1u) & 1u], n0 + t - 1u);
        sts_tile(osm[t & 1u], v);
        __syncthreads();
    }
    stg_tile(osm[1], n0 + 3u);
}

extern "C" void kernel_launch(void* const* d_in, const int* in_sizes, int n_in,
                              void* d_out, int out_size) {
    (void)in_sizes; (void)n_in; (void)out_size;
    arnold_v8_kernel<<<BLOCKS, THREADS>>>((const float*)d_in[0], (float*)d_out);
}

// round 9
// speedup vs baseline: 1.0389x; 1.0389x over previous
#include <cuda_runtime.h>

// ArnoldCat ^7, n=1024: out[a,b] <- in[(239a+169b)&1023, (338a+239b)&1023].
//
// Lattice basis: (a,b) = (169k', j'-239k'), source = (169j', k'+239j').
// Tile (m,n): k' = 32m+k (k<32), j' = 64n+j (j<64). Exact partition of both
// input and output (no overlap, single-touch traffic, all lanes active).
//   Phase 1: row j -> source row 169j'&1023, 96 consecutive floats at
//            3*((32m+239j')&1023); element f=3k+c -> osm[195k + c + 3j].
//   Phase 2: output row a=169k'&1023, 192 consecutive floats (768B burst) at
//            3*((64n-239k')&1023); float f'=3j+c read from osm[195k + f'].
// Stride 195 ≡ 3 (mod 32): STS addr ≡ lane+3j, LDS addr ≡ 3k+lane (mod 32) —
// conflict-free both phases. Row-wrap tests are warp-uniform.

static constexpr unsigned THREADS = 512u;
static constexpr unsigned BLOCKS  = 16u * 32u * 16u;   // batch x m(32) x n(16)
static constexpr unsigned IMG_F   = 1024u * 3072u;
static constexpr unsigned P       = 195u;              // smem floats per k-row

__global__ void __launch_bounds__(THREADS, 4)
arnold_v9_kernel(const float* __restrict__ in, float* __restrict__ out) {
    __shared__ float osm[32u * P];                     // 24960 B

    const unsigned id    = blockIdx.x;
    const unsigned n     = id & 15u;
    const unsigned m     = (id >> 4) & 31u;
    const unsigned batch = id >> 9;
    const unsigned lane  = threadIdx.x & 31u;
    const unsigned warp  = threadIdx.x >> 5;           // 0..15

    const float* inb = in + batch * IMG_F;

    // element f = lane+32t -> smem base 195*(f/3) + f%3
    unsigned sb[3];
    #pragma unroll
    for (unsigned t = 0; t < 3u; ++t) {
        unsigned f = lane + 32u * t;
        unsigned k = f / 3u;
        sb[t] = P * k + (f - 3u * k);
    }

    // ---- Phase 1: 12 independent LDGs (rows j = warp + 16r) ----
    float v[4][3];
    #pragma unroll
    for (unsigned r = 0; r < 4u; ++r) {
        unsigned j   = warp + 16u * r;                 // 0..63
        unsigned jp  = 64u * n + j;
        unsigned ry  = (169u * jp) & 1023u;
        unsigned cb3 = ((32u * m + 239u * jp) & 1023u) * 3u;
        const float* rowp = inb + ry * 3072u;
        if (cb3 <= 3072u - 96u) {                      // warp-uniform fast path
            const float* seg = rowp + cb3 + lane;
            v[r][0] = __ldcs(seg);
            v[r][1] = __ldcs(seg + 32u);
            v[r][2] = __ldcs(seg + 64u);
        } else {                                       // row wraps (rare)
            #pragma unroll
            for (unsigned t = 0; t < 3u; ++t) {
                unsigned o = cb3 + lane + 32u * t;
                if (o >= 3072u) o -= 3072u;
                v[r][t] = __ldcs(rowp + o);
            }
        }
    }
    #pragma unroll
    for (unsigned r = 0; r < 4u; ++r) {                // conflict-free STS
        unsigned j3 = 3u * (warp + 16u * r);
        #pragma unroll
        for (unsigned t = 0; t < 3u; ++t)
            osm[sb[t] + j3] = v[r][t];
    }
    __syncthreads();

    // ---- Phase 2: 32 output rows, 192 contiguous floats each (768B burst) ----
    float* outb = out + batch * IMG_F;
    #pragma unroll
    for (unsigned it = 0; it < 2u; ++it) {
        unsigned k   = warp + 16u * it;                // 0..31
        unsigned kp  = 32u * m + k;
        unsigned a   = (169u * kp) & 1023u;
        unsigned ob3 = ((64u * n - 239u * kp) & 1023u) * 3u;
        const float* sr = osm + P * k + lane;          // base + immediate offsets
        float r0 = sr[0],   r1 = sr[32],  r2 = sr[64];
        float r3 = sr[96],  r4 = sr[128], r5 = sr[160];
        float* orow = outb + a * 3072u;
        if (ob3 <= 3072u - 192u) {                     // warp-uniform fast path
            float* seg = orow + ob3 + lane;
            __stcs(seg,        r0);
            __stcs(seg + 32u,  r1);
            __stcs(seg + 64u,  r2);
            __stcs(seg + 96u,  r3);
            __stcs(seg + 128u, r4);
            __stcs(seg + 160u, r5);
        } else {                                       // row wraps (~6%)
            float rr[6] = {r0, r1, r2, r3, r4, r5};
            #pragma unroll
            for (unsigned t = 0; t < 6u; ++t) {
                unsigned o = ob3 + lane + 32u * t;
                if (o >= 3072u) o -= 3072u;
                __stcs(orow + o, rr[t]);
            }
        }
    }
}

extern "C" void kernel_launch(void* const* d_in, const int* in_sizes, int n_in,
                              void* d_out, int out_size) {
    (void)in_sizes; (void)n_in; (void)out_size;
    arnold_v9_kernel<<<BLOCKS, THREADS>>>((const float*)d_in[0], (float*)d_out);
}